// round 3
// baseline (speedup 1.0000x reference)
#include <cuda_runtime.h>

// Guided filter, fully fused, SMEM-free, warp-sliding, 4 columns per lane.
// One warp covers 128 loaded columns (lane k -> cols cbase+4k..+3), outputs the
// middle 120 (lanes 1..30), and slides down CHUNK_H rows. Horizontal 3-sums are
// in-register with one shuffle pair per quantity per row; vertical 3-sums use
// 3-deep register rings. Replication padding: stage 1 via clamped loads at
// edge lanes, stage 2 via pl/pr selects (col 0 / col 1023) and row ring copies.

#define W 1024
#define H 1024
#define EPSF 1e-6f
#define C9 (1.0f / 9.0f)

#define OUTC 120            // output columns per warp (lanes 1..30 * 4)
#define BANDS 9             // ceil(1024 / 120)
#define CHUNK_H 128
#define CHUNKS (H / CHUNK_H)
#define WPB 4               // warps per block (128 threads)
#define NPLANES 24
#define UNITS (NPLANES * BANDS * CHUNKS)   // 1728 warps
#define NBLOCKS (UNITS / WPB)              // 432 blocks

__device__ __forceinline__ float4 h3(float4 v, float vl, float vr) {
    float4 r;
    r.x = vl  + v.x + v.y;
    r.y = v.x + v.y + v.z;
    r.z = v.y + v.z + v.w;
    r.w = v.z + v.w + vr;
    return r;
}
__device__ __forceinline__ float4 h3s(float4 v) {
    float vl = __shfl_up_sync(0xffffffffu, v.w, 1);   // lane0 keeps own (halo, unused)
    float vr = __shfl_down_sync(0xffffffffu, v.x, 1); // lane31 keeps own
    return h3(v, vl, vr);
}
__device__ __forceinline__ float4 add3(float4 a, float4 b, float4 c) {
    return make_float4(a.x + b.x + c.x, a.y + b.y + c.y,
                       a.z + b.z + c.z, a.w + b.w + c.w);
}
__device__ __forceinline__ void ab1(float sx, float sy, float sxy, float sxx,
                                    float& A, float& B) {
    float mx = sx * C9, my = sy * C9;
    float cov = fmaf(sxy, C9, -(mx * my));
    float var = fmaf(sxx, C9, fmaf(-mx, mx, EPSF));
    A = __fdividef(cov, var);
    B = fmaf(-A, mx, my);
}
__device__ __forceinline__ void abrow(float4 Sx, float4 Sy, float4 Sxy, float4 Sxx,
                                      bool pl, bool pr, float4& hA, float4& hB) {
    float4 A, B;
    ab1(Sx.x, Sy.x, Sxy.x, Sxx.x, A.x, B.x);
    ab1(Sx.y, Sy.y, Sxy.y, Sxx.y, A.y, B.y);
    ab1(Sx.z, Sy.z, Sxy.z, Sxx.z, A.z, B.z);
    ab1(Sx.w, Sy.w, Sxy.w, Sxx.w, A.w, B.w);
    float Al = __shfl_up_sync(0xffffffffu, A.w, 1);
    float Ar = __shfl_down_sync(0xffffffffu, A.x, 1);
    float Bl = __shfl_up_sync(0xffffffffu, B.w, 1);
    float Br = __shfl_down_sync(0xffffffffu, B.x, 1);
    if (pl) { Al = A.x; Bl = B.x; }   // A(-1) := A(0)
    if (pr) { Ar = A.w; Br = B.w; }   // A(1024) := A(1023)
    hA = h3(A, Al, Ar);
    hB = h3(B, Bl, Br);
}
__device__ __forceinline__ float4 ldv(const float* rowp, int cfirst, bool inb,
                                      int cc0, int cc1, int cc2, int cc3) {
    if (inb) return *reinterpret_cast<const float4*>(rowp + cfirst);
    return make_float4(rowp[cc0], rowp[cc1], rowp[cc2], rowp[cc3]);
}

__global__ __launch_bounds__(128, 3) void gf_kernel(const float* __restrict__ x,
                                                    const float* __restrict__ y,
                                                    float* __restrict__ out)
{
    const int wid  = threadIdx.x >> 5;
    const int lane = threadIdx.x & 31;
    const int g    = blockIdx.x * WPB + wid;

    const int plane = g / (BANDS * CHUNKS);
    const int rem   = g - plane * (BANDS * CHUNKS);
    const int band  = rem / CHUNKS;
    const int chunk = rem - band * CHUNKS;

    const int cfirst = band * OUTC - 4 + lane * 4;     // first of this lane's 4 cols
    const bool inb = (cfirst >= 0) && (cfirst + 3 < W);
    const int cc0 = min(max(cfirst + 0, 0), W - 1);
    const int cc1 = min(max(cfirst + 1, 0), W - 1);
    const int cc2 = min(max(cfirst + 2, 0), W - 1);
    const int cc3 = min(max(cfirst + 3, 0), W - 1);
    const int r0  = chunk * CHUNK_H;
    const bool pl = (cfirst == 0);       // elem .x is image col 0
    const bool pr = (cfirst == W - 4);   // elem .w is image col 1023
    const bool do_store = (lane >= 1) && (lane <= 30) && (cfirst < W);

    const size_t pb = (size_t)plane * (size_t)(W * H);
    const float* px = x + pb;
    const float* py = y + pb;
    float* po = out + pb + (size_t)r0 * W + cfirst;

    // 3-deep register rings (rotated by the unrolled STEP slots, never indexed
    // dynamically)
    float4 hx[3], hy[3], hxy[3], hxx[3], hA[3], hB[3], xc[3];

#define HQROW(rowi, HX, HY, HXY, HXX, XCV) { \
    const float* rp = px + (size_t)(rowi) * W; \
    const float* rq = py + (size_t)(rowi) * W; \
    float4 xv = ldv(rp, cfirst, inb, cc0, cc1, cc2, cc3); \
    float4 yv = ldv(rq, cfirst, inb, cc0, cc1, cc2, cc3); \
    float4 xyv = make_float4(xv.x * yv.x, xv.y * yv.y, xv.z * yv.z, xv.w * yv.w); \
    float4 xxv = make_float4(xv.x * xv.x, xv.y * xv.y, xv.z * xv.z, xv.w * xv.w); \
    HX = h3s(xv); HY = h3s(yv); HXY = h3s(xyv); HXX = h3s(xxv); XCV = xv; }

    // ---------------- prologue: rows r0-2 .. r0+1, A rows r0-1, r0 ----------------
    {
        float4 tx0, ty0, txy0, txx0, tx1, ty1, txy1, txx1, dummy;
        HQROW(max(r0 - 2, 0), tx0, ty0, txy0, txx0, dummy)
        HQROW(max(r0 - 1, 0), tx1, ty1, txy1, txx1, dummy)
        HQROW(r0,     hx[0], hy[0], hxy[0], hxx[0], xc[0])
        HQROW(r0 + 1, hx[1], hy[1], hxy[1], hxx[1], xc[1])
        abrow(add3(tx0, tx1, hx[0]), add3(ty0, ty1, hy[0]),
              add3(txy0, txy1, hxy[0]), add3(txx0, txx1, hxx[0]),
              pl, pr, hA[0], hB[0]);                       // A row r0-1
        abrow(add3(tx1, hx[0], hx[1]), add3(ty1, hy[0], hy[1]),
              add3(txy1, hxy[0], hxy[1]), add3(txx1, hxx[0], hxx[1]),
              pl, pr, hA[1], hB[1]);                       // A row r0
        if (r0 == 0) { hA[0] = hA[1]; hB[0] = hB[1]; }     // top: A(-1) := A(0)
    }

    int rowcur = r0 + 2;   // next input row to load (clamped at H-1)

    // STEP i: loads input row min(r0+i+2, H-1) into slot ic2, computes A row
    // r0+i+1 into slot ic2, emits output row r0+i from slots (ia, ib, ic2).
#define STEP(ia, ib, ic2, i) { \
    const int rr = r0 + (i); \
    HQROW(rowcur, hx[ic2], hy[ic2], hxy[ic2], hxx[ic2], xc[ic2]) \
    if (rowcur < H - 1) rowcur++; \
    float4 Sx  = add3(hx[ia],  hx[ib],  hx[ic2]); \
    float4 Sy  = add3(hy[ia],  hy[ib],  hy[ic2]); \
    float4 Sxy = add3(hxy[ia], hxy[ib], hxy[ic2]); \
    float4 Sxx = add3(hxx[ia], hxx[ib], hxx[ic2]); \
    float4 hAn, hBn; \
    abrow(Sx, Sy, Sxy, Sxx, pl, pr, hAn, hBn); \
    if (rr + 1 >= H) { hAn = hA[ib]; hBn = hB[ib]; }  /* bottom: A(1024):=A(1023) */ \
    hA[ic2] = hAn; hB[ic2] = hBn; \
    float4 SA = add3(hA[ia], hA[ib], hAn); \
    float4 SB = add3(hB[ia], hB[ib], hBn); \
    float4 xcv = xc[ia]; \
    float4 res; \
    res.x = fminf(fmaxf(truncf(fmaf(SA.x * C9, xcv.x, SB.x * C9)), 0.f), 255.f); \
    res.y = fminf(fmaxf(truncf(fmaf(SA.y * C9, xcv.y, SB.y * C9)), 0.f), 255.f); \
    res.z = fminf(fmaxf(truncf(fmaf(SA.z * C9, xcv.z, SB.z * C9)), 0.f), 255.f); \
    res.w = fminf(fmaxf(truncf(fmaf(SA.w * C9, xcv.w, SB.w * C9)), 0.f), 255.f); \
    if (do_store) *reinterpret_cast<float4*>(po) = res; \
    po += W; }

    // 128 rows: 42 triples (i = 0..125) + i = 126, 127
    for (int i = 0; i < CHUNK_H - 2; i += 3) {
        STEP(0, 1, 2, i)
        STEP(1, 2, 0, i + 1)
        STEP(2, 0, 1, i + 2)
    }
    STEP(0, 1, 2, CHUNK_H - 2)
    STEP(1, 2, 0, CHUNK_H - 1)
#undef STEP
#undef HQROW
}

extern "C" void kernel_launch(void* const* d_in, const int* in_sizes, int n_in,
                              void* d_out, int out_size) {
    const float* x = (const float*)d_in[0];
    const float* y = (const float*)d_in[1];
    float* out     = (float*)d_out;

    gf_kernel<<<NBLOCKS, 32 * WPB>>>(x, y, out);
}

// round 4
// speedup vs baseline: 1.0835x; 1.0835x over previous
#include <cuda_runtime.h>

// Guided filter, fully fused, SMEM-free, warp-sliding, 2 columns per lane.
// One warp covers 64 loaded columns (lane k -> cols cbase+2k, +1), outputs the
// middle 60 (lanes 1..30), slides down CHUNK_H rows. Horizontal 3-sums via one
// shuffle pair per quantity per row; vertical 3-sums via 3-deep register rings.
// Column replication (both stages) via in-warp selects at cols 0/1023; row
// replication via clamped row indices (stage 1) and ring copies (stage 2).

#define W 1024
#define H 1024
#define EPSF 1e-6f
#define C9 (1.0f / 9.0f)

#define OUTC 60
#define BANDS 18            // ceil(1024/60) = 18 (last band partial)
#define CHUNK_H 64
#define CHUNKS (H / CHUNK_H)               // 16
#define WPB 8               // 256 threads
#define NPLANES 24
#define UNITS (NPLANES * BANDS * CHUNKS)   // 6912 warps
#define NBLOCKS (UNITS / WPB)              // 864

__device__ __forceinline__ float2 ld2(const float* p, int row) {
    return *reinterpret_cast<const float2*>(p + (size_t)row * W);
}
// horizontal 3-sum with edge-replication selects
__device__ __forceinline__ float2 h3s(float2 v, bool pl, bool pr) {
    float vl = __shfl_up_sync(0xffffffffu, v.y, 1);
    float vr = __shfl_down_sync(0xffffffffu, v.x, 1);
    if (pl) vl = v.x;     // col -1 := col 0
    if (pr) vr = v.y;     // col 1024 := col 1023
    float m = v.x + v.y;
    return make_float2(vl + m, m + vr);
}
__device__ __forceinline__ float2 add3(float2 a, float2 b, float2 c) {
    return make_float2(a.x + b.x + c.x, a.y + b.y + c.y);
}
__device__ __forceinline__ void ab1(float sx, float sy, float sxy, float sxx,
                                    float& A, float& B) {
    float mx = sx * C9, my = sy * C9;
    float cov = fmaf(sxy, C9, -(mx * my));
    float var = fmaf(sxx, C9, fmaf(-mx, mx, EPSF));
    A = __fdividef(cov, var);
    B = fmaf(-A, mx, my);
}
__device__ __forceinline__ void abrow(float2 Sx, float2 Sy, float2 Sxy, float2 Sxx,
                                      bool pl, bool pr, float2& hA, float2& hB) {
    float2 A, B;
    ab1(Sx.x, Sy.x, Sxy.x, Sxx.x, A.x, B.x);
    ab1(Sx.y, Sy.y, Sxy.y, Sxx.y, A.y, B.y);
    float Al = __shfl_up_sync(0xffffffffu, A.y, 1);
    float Ar = __shfl_down_sync(0xffffffffu, A.x, 1);
    float Bl = __shfl_up_sync(0xffffffffu, B.y, 1);
    float Br = __shfl_down_sync(0xffffffffu, B.x, 1);
    if (pl) { Al = A.x; Bl = B.x; }
    if (pr) { Ar = A.y; Br = B.y; }
    float ma = A.x + A.y, mb = B.x + B.y;
    hA = make_float2(Al + ma, ma + Ar);
    hB = make_float2(Bl + mb, mb + Br);
}

__global__ __launch_bounds__(256) void gf_kernel(const float* __restrict__ x,
                                                 const float* __restrict__ y,
                                                 float* __restrict__ out)
{
    const int wid  = threadIdx.x >> 5;
    const int lane = threadIdx.x & 31;
    const int g    = blockIdx.x * WPB + wid;

    const int plane = g / (BANDS * CHUNKS);
    const int rem   = g - plane * (BANDS * CHUNKS);
    const int band  = rem / CHUNKS;
    const int chunk = rem - band * CHUNKS;

    const int cfirst = band * OUTC - 2 + lane * 2;       // this lane's 2 cols
    const int cl     = min(max(cfirst, 0), W - 2);       // clamped aligned load col
    const int r0     = chunk * CHUNK_H;
    const bool pl = (cfirst == 0);
    const bool pr = (cfirst == W - 2);
    const bool do_store = (lane >= 1) && (lane <= 30) && (cfirst >= 0) && (cfirst < W);

    const size_t pb = (size_t)plane * (size_t)(W * H);
    const float* px = x + pb + cl;
    const float* py = y + pb + cl;
    float* po = out + pb + (size_t)r0 * W + cfirst;

    // 3-deep register rings (rotated via the unrolled STEP slot arguments)
    float2 hx[3], hy[3], hxy[3], hxx[3], hA[3], hB[3], xc[3];

#define HQ(xv, yv, HX, HY, HXY, HXX) { \
    float2 xyv = make_float2(xv.x * yv.x, xv.y * yv.y); \
    float2 xxv = make_float2(xv.x * xv.x, xv.y * xv.y); \
    HX = h3s(xv, pl, pr); HY = h3s(yv, pl, pr); \
    HXY = h3s(xyv, pl, pr); HXX = h3s(xxv, pl, pr); }

    // ---------------- prologue: rows r0-2 .. r0+1, A rows r0-1, r0 ----------------
    {
        float2 tx0, ty0, txy0, txx0, tx1, ty1, txy1, txx1;
        { float2 xv = ld2(px, max(r0 - 2, 0)), yv = ld2(py, max(r0 - 2, 0));
          HQ(xv, yv, tx0, ty0, txy0, txx0) }
        { float2 xv = ld2(px, max(r0 - 1, 0)), yv = ld2(py, max(r0 - 1, 0));
          HQ(xv, yv, tx1, ty1, txy1, txx1) }
        { float2 xv = ld2(px, r0), yv = ld2(py, r0);
          HQ(xv, yv, hx[0], hy[0], hxy[0], hxx[0]) xc[0] = xv; }
        { float2 xv = ld2(px, r0 + 1), yv = ld2(py, r0 + 1);
          HQ(xv, yv, hx[1], hy[1], hxy[1], hxx[1]) xc[1] = xv; }
        abrow(add3(tx0, tx1, hx[0]), add3(ty0, ty1, hy[0]),
              add3(txy0, txy1, hxy[0]), add3(txx0, txx1, hxx[0]),
              pl, pr, hA[0], hB[0]);                        // A row r0-1
        abrow(add3(tx1, hx[0], hx[1]), add3(ty1, hy[0], hy[1]),
              add3(txy1, hxy[0], hxy[1]), add3(txx1, hxx[0], hxx[1]),
              pl, pr, hA[1], hB[1]);                        // A row r0
        if (r0 == 0) { hA[0] = hA[1]; hB[0] = hB[1]; }      // top: A(-1) := A(0)
    }

    // software-pipelined input row (one row ahead)
    int rowcur = r0 + 2;                 // row held in (pxv, pyv)
    float2 pxv = ld2(px, rowcur);
    float2 pyv = ld2(py, rowcur);

    // STEP i: consumes prefetched input row min(r0+i+2, H-1), prefetches the
    // next one, computes A row r0+i+1 into slot ic2, emits output row r0+i.
#define STEP(ia, ib, ic2, i) { \
    const int rr = r0 + (i); \
    float2 xv = pxv, yv = pyv; \
    rowcur = (rowcur < H - 1) ? rowcur + 1 : rowcur; \
    pxv = ld2(px, rowcur); pyv = ld2(py, rowcur); \
    HQ(xv, yv, hx[ic2], hy[ic2], hxy[ic2], hxx[ic2]) \
    xc[ic2] = xv; \
    float2 Sx  = add3(hx[ia],  hx[ib],  hx[ic2]); \
    float2 Sy  = add3(hy[ia],  hy[ib],  hy[ic2]); \
    float2 Sxy = add3(hxy[ia], hxy[ib], hxy[ic2]); \
    float2 Sxx = add3(hxx[ia], hxx[ib], hxx[ic2]); \
    float2 hAn, hBn; \
    abrow(Sx, Sy, Sxy, Sxx, pl, pr, hAn, hBn); \
    if (rr + 1 >= H) { hAn = hA[ib]; hBn = hB[ib]; }  /* bottom: A(H):=A(H-1) */ \
    hA[ic2] = hAn; hB[ic2] = hBn; \
    float2 SA = add3(hA[ia], hA[ib], hAn); \
    float2 SB = add3(hB[ia], hB[ib], hBn); \
    float2 xcv = xc[ia]; \
    float2 res; \
    res.x = fminf(fmaxf(truncf(fmaf(SA.x * C9, xcv.x, SB.x * C9)), 0.f), 255.f); \
    res.y = fminf(fmaxf(truncf(fmaf(SA.y * C9, xcv.y, SB.y * C9)), 0.f), 255.f); \
    if (do_store) *reinterpret_cast<float2*>(po) = res; \
    po += W; }

    // CHUNK_H = 64 rows: 21 triples (i = 0..62) + i = 63 (63 % 3 == 0)
    for (int i = 0; i < CHUNK_H - 2; i += 3) {
        STEP(0, 1, 2, i)
        STEP(1, 2, 0, i + 1)
        STEP(2, 0, 1, i + 2)
    }
    STEP(0, 1, 2, CHUNK_H - 1)
#undef STEP
#undef HQ
}

extern "C" void kernel_launch(void* const* d_in, const int* in_sizes, int n_in,
                              void* d_out, int out_size) {
    const float* x = (const float*)d_in[0];
    const float* y = (const float*)d_in[1];
    float* out     = (float*)d_out;

    gf_kernel<<<NBLOCKS, 32 * WPB>>>(x, y, out);
}

// round 5
// speedup vs baseline: 1.2207x; 1.1267x over previous
#include <cuda_runtime.h>

// Guided filter, fully fused, SMEM-free warp-sliding (round-2 skeleton).
// One warp = 32-lane column band (28 stored outputs, 2-lane halo per side),
// slides down CHUNK_H rows. Stage-1 horizontal 3-sums from 4 shuffles/row
// (xl,xr,yl,yr only; xy/xx h-sums rebuilt via FMA). Vertical 3-sums from
// 3-deep register rings. Replication: stage 1 via clamped lane columns
// (duplicated edge lanes make shuffles return the pad), stage 2 via pl/pr
// selects at cols 0/1023 and ring copies at rows 0/1023.

#define W 1024
#define H 1024
#define EPSF 1e-6f
#define C9 (1.0f / 9.0f)

#define OUTC 28
#define BANDS 37                            // ceil(1024/28)
#define CHUNK_H 64
#define CHUNKS (H / CHUNK_H)                // 16
#define WPB 8                               // 256 threads
#define UNITS (24 * BANDS * CHUNKS)         // 14208 warps
#define NBLOCKS (UNITS / WPB)               // 1776 = 2 full waves @ 6 blocks/SM

__global__ __launch_bounds__(256, 6) void gf_kernel(const float* __restrict__ x,
                                                    const float* __restrict__ y,
                                                    float* __restrict__ out)
{
    const int wid  = threadIdx.x >> 5;
    const int lane = threadIdx.x & 31;
    const int g    = blockIdx.x * WPB + wid;

    const int plane = g / (BANDS * CHUNKS);
    const int rem   = g - plane * (BANDS * CHUNKS);
    const int band  = rem / CHUNKS;
    const int chunk = rem - band * CHUNKS;

    const int cbase = band * OUTC - 2;
    const int icr   = cbase + lane;                 // raw column of this lane
    const int ic    = min(max(icr, 0), W - 1);      // clamped load column
    const int r0    = chunk * CHUNK_H;

    const bool pl = (icr == 0);                     // stage-2 left replication
    const bool pr = (icr == W - 1);                 // stage-2 right replication
    const bool do_store = (lane >= 2) && (lane <= 29) && (icr >= 0) && (icr < W);

    const size_t pb = (size_t)plane * (size_t)(W * H);
    const float* px = x + pb + ic;
    const float* py = y + pb + ic;
    float* po = out + pb + (size_t)r0 * W + ic;     // ic == icr wherever stored

    // 3-deep register rings (rotated via unrolled STEP slot args, never
    // dynamically indexed)
    float hx[3], hy[3], hxy[3], hxx[3], hA[3], hB[3], xc[3];

    // Horizontal sums from 4 shuffles: neighbors of x and y only.
#define HQ(xv, yv, HX, HY, HXY, HXX) { \
    float xl = __shfl_up_sync(0xffffffffu, xv, 1); \
    float xr = __shfl_down_sync(0xffffffffu, xv, 1); \
    float yl = __shfl_up_sync(0xffffffffu, yv, 1); \
    float yr = __shfl_down_sync(0xffffffffu, yv, 1); \
    HX = xl + xv + xr; \
    HY = yl + yv + yr; \
    HXY = fmaf(xl, yl, fmaf(xr, yr, xv * yv)); \
    HXX = fmaf(xl, xl, fmaf(xr, xr, xv * xv)); }

#define ABROW(Sx, Sy, Sxy, Sxx, HA, HB) { \
    float mx = (Sx) * C9, my = (Sy) * C9; \
    float cov = fmaf((Sxy), C9, -(mx * my)); \
    float var = fmaf((Sxx), C9, fmaf(-mx, mx, EPSF)); \
    float Av = __fdividef(cov, var); \
    float Bv = fmaf(-Av, mx, my); \
    float Al = __shfl_up_sync(0xffffffffu, Av, 1); \
    float Ar = __shfl_down_sync(0xffffffffu, Av, 1); \
    float Bl = __shfl_up_sync(0xffffffffu, Bv, 1); \
    float Br = __shfl_down_sync(0xffffffffu, Bv, 1); \
    if (pl) { Al = Av; Bl = Bv; } \
    if (pr) { Ar = Av; Br = Bv; } \
    HA = Al + Av + Ar; \
    HB = Bl + Bv + Br; }

    // ---------------- prologue: rows r0-2 .. r0+1, A rows r0-1, r0 ----------------
    {
        float tx0, ty0, txy0, txx0, tx1, ty1, txy1, txx1;
        { int rc = max(r0 - 2, 0);
          float xv = px[(size_t)rc * W], yv = py[(size_t)rc * W];
          HQ(xv, yv, tx0, ty0, txy0, txx0) }
        { int rc = max(r0 - 1, 0);
          float xv = px[(size_t)rc * W], yv = py[(size_t)rc * W];
          HQ(xv, yv, tx1, ty1, txy1, txx1) }
        { float xv = px[(size_t)r0 * W], yv = py[(size_t)r0 * W];
          HQ(xv, yv, hx[0], hy[0], hxy[0], hxx[0]) xc[0] = xv; }
        { float xv = px[(size_t)(r0 + 1) * W], yv = py[(size_t)(r0 + 1) * W];
          HQ(xv, yv, hx[1], hy[1], hxy[1], hxx[1]) xc[1] = xv; }
        ABROW(tx0 + tx1 + hx[0], ty0 + ty1 + hy[0],
              txy0 + txy1 + hxy[0], txx0 + txx1 + hxx[0], hA[0], hB[0])
        ABROW(tx1 + hx[0] + hx[1], ty1 + hy[0] + hy[1],
              txy1 + hxy[0] + hxy[1], txx1 + hxx[0] + hxx[1], hA[1], hB[1])
        if (r0 == 0) { hA[0] = hA[1]; hB[0] = hB[1]; }   // top: A(-1) := A(0)
    }

    // software-pipelined input row (one row ahead)
    int rowcur = r0 + 2;
    float pxv = px[(size_t)rowcur * W];
    float pyv = py[(size_t)rowcur * W];

    // STEP i: consumes prefetched row min(r0+i+2, H-1), prefetches the next,
    // computes A row r0+i+1 into slot ic2, emits output row r0+i.
#define STEP(ia, ib, ic2, i) { \
    const int rr = r0 + (i); \
    float xv = pxv, yv = pyv; \
    rowcur = (rowcur < H - 1) ? rowcur + 1 : rowcur; \
    pxv = px[(size_t)rowcur * W]; \
    pyv = py[(size_t)rowcur * W]; \
    HQ(xv, yv, hx[ic2], hy[ic2], hxy[ic2], hxx[ic2]) \
    xc[ic2] = xv; \
    float hAn, hBn; \
    ABROW(hx[ia] + hx[ib] + hx[ic2], hy[ia] + hy[ib] + hy[ic2], \
          hxy[ia] + hxy[ib] + hxy[ic2], hxx[ia] + hxx[ib] + hxx[ic2], hAn, hBn) \
    if (rr + 1 >= H) { hAn = hA[ib]; hBn = hB[ib]; }   /* bottom: A(H):=A(H-1) */ \
    hA[ic2] = hAn; hB[ic2] = hBn; \
    float SA = hA[ia] + hA[ib] + hAn; \
    float SB = hB[ia] + hB[ib] + hBn; \
    float res = fmaf(SA * C9, xc[ia], SB * C9); \
    res = fminf(fmaxf(truncf(res), 0.0f), 255.0f); \
    if (do_store) *po = res; \
    po += W; }

    // CHUNK_H = 64 rows: 21 triples (i = 0..62) + i = 63 (63 % 3 == 0)
    for (int i = 0; i < CHUNK_H - 2; i += 3) {
        STEP(0, 1, 2, i)
        STEP(1, 2, 0, i + 1)
        STEP(2, 0, 1, i + 2)
    }
    STEP(0, 1, 2, CHUNK_H - 1)
#undef STEP
#undef ABROW
#undef HQ
}

extern "C" void kernel_launch(void* const* d_in, const int* in_sizes, int n_in,
                              void* d_out, int out_size) {
    const float* x = (const float*)d_in[0];
    const float* y = (const float*)d_in[1];
    float* out     = (float*)d_out;

    gf_kernel<<<NBLOCKS, 32 * WPB>>>(x, y, out);
}

// round 6
// speedup vs baseline: 1.2288x; 1.0066x over previous
#include <cuda_runtime.h>

// Guided filter, fully fused, SMEM-free warp-sliding.
// Round-2 schedule (CHUNK_H=128, 888 blocks = exactly one wave at 6 blocks/SM)
// + round-5 inner loop (8 shuffles/step, one-row software prefetch).
// One warp = 32-lane column band (28 stored outputs, 2-lane halo per side).
// Replication: stage 1 via clamped lane columns / clamped prologue rows,
// stage 2 via pl/pr selects at cols 0/1023 and ring copies at rows 0/1023.

#define W 1024
#define H 1024
#define EPSF 1e-6f
#define C9 (1.0f / 9.0f)

#define OUTC 28
#define BANDS 37                            // ceil(1024/28)
#define CHUNK_H 128
#define CHUNKS (H / CHUNK_H)                // 8
#define WPB 8                               // 256 threads
#define UNITS (24 * BANDS * CHUNKS)         // 7104 warps
#define NBLOCKS (UNITS / WPB)               // 888 = 148 SMs * 6 blocks (1 wave)

__global__ __launch_bounds__(256, 6) void gf_kernel(const float* __restrict__ x,
                                                    const float* __restrict__ y,
                                                    float* __restrict__ out)
{
    const int wid  = threadIdx.x >> 5;
    const int lane = threadIdx.x & 31;
    const int g    = blockIdx.x * WPB + wid;

    const int plane = g / (BANDS * CHUNKS);
    const int rem   = g - plane * (BANDS * CHUNKS);
    const int band  = rem / CHUNKS;
    const int chunk = rem - band * CHUNKS;

    const int cbase = band * OUTC - 2;
    const int icr   = cbase + lane;                 // raw column of this lane
    const int ic    = min(max(icr, 0), W - 1);      // clamped load column
    const int r0    = chunk * CHUNK_H;

    const bool pl = (icr == 0);                     // stage-2 left replication
    const bool pr = (icr == W - 1);                 // stage-2 right replication
    const bool do_store = (lane >= 2) && (lane <= 29) && (icr >= 0) && (icr < W);

    const size_t pb = (size_t)plane * (size_t)(W * H);
    const float* px = x + pb + ic;
    const float* py = y + pb + ic;
    float* po = out + pb + (size_t)r0 * W + ic;     // ic == icr wherever stored

    // 3-deep register rings (rotated via unrolled STEP slot args, never
    // dynamically indexed)
    float hx[3], hy[3], hxy[3], hxx[3], hA[3], hB[3], xc[3];

    // Horizontal sums from 4 shuffles: neighbors of x and y only; the xy / xx
    // horizontal sums are rebuilt from neighbor values with FMAs.
#define HQ(xv, yv, HX, HY, HXY, HXX) { \
    float xl = __shfl_up_sync(0xffffffffu, xv, 1); \
    float xr = __shfl_down_sync(0xffffffffu, xv, 1); \
    float yl = __shfl_up_sync(0xffffffffu, yv, 1); \
    float yr = __shfl_down_sync(0xffffffffu, yv, 1); \
    HX = xl + xv + xr; \
    HY = yl + yv + yr; \
    HXY = fmaf(xl, yl, fmaf(xr, yr, xv * yv)); \
    HXX = fmaf(xl, xl, fmaf(xr, xr, xv * xv)); }

#define ABROW(Sx, Sy, Sxy, Sxx, HA, HB) { \
    float mx = (Sx) * C9, my = (Sy) * C9; \
    float cov = fmaf((Sxy), C9, -(mx * my)); \
    float var = fmaf((Sxx), C9, fmaf(-mx, mx, EPSF)); \
    float Av = __fdividef(cov, var); \
    float Bv = fmaf(-Av, mx, my); \
    float Al = __shfl_up_sync(0xffffffffu, Av, 1); \
    float Ar = __shfl_down_sync(0xffffffffu, Av, 1); \
    float Bl = __shfl_up_sync(0xffffffffu, Bv, 1); \
    float Br = __shfl_down_sync(0xffffffffu, Bv, 1); \
    if (pl) { Al = Av; Bl = Bv; } \
    if (pr) { Ar = Av; Br = Bv; } \
    HA = Al + Av + Ar; \
    HB = Bl + Bv + Br; }

    // ---------------- prologue: rows r0-2 .. r0+1, A rows r0-1, r0 ----------------
    {
        float tx0, ty0, txy0, txx0, tx1, ty1, txy1, txx1;
        { int rc = max(r0 - 2, 0);
          float xv = px[(size_t)rc * W], yv = py[(size_t)rc * W];
          HQ(xv, yv, tx0, ty0, txy0, txx0) }
        { int rc = max(r0 - 1, 0);
          float xv = px[(size_t)rc * W], yv = py[(size_t)rc * W];
          HQ(xv, yv, tx1, ty1, txy1, txx1) }
        { float xv = px[(size_t)r0 * W], yv = py[(size_t)r0 * W];
          HQ(xv, yv, hx[0], hy[0], hxy[0], hxx[0]) xc[0] = xv; }
        { float xv = px[(size_t)(r0 + 1) * W], yv = py[(size_t)(r0 + 1) * W];
          HQ(xv, yv, hx[1], hy[1], hxy[1], hxx[1]) xc[1] = xv; }
        ABROW(tx0 + tx1 + hx[0], ty0 + ty1 + hy[0],
              txy0 + txy1 + hxy[0], txx0 + txx1 + hxx[0], hA[0], hB[0])
        ABROW(tx1 + hx[0] + hx[1], ty1 + hy[0] + hy[1],
              txy1 + hxy[0] + hxy[1], txx1 + hxx[0] + hxx[1], hA[1], hB[1])
        if (r0 == 0) { hA[0] = hA[1]; hB[0] = hB[1]; }   // top: A(-1) := A(0)
    }

    // software-pipelined input row (one row ahead)
    int rowcur = r0 + 2;
    float pxv = px[(size_t)rowcur * W];
    float pyv = py[(size_t)rowcur * W];

    // STEP i: consumes prefetched row min(r0+i+2, H-1), prefetches the next,
    // computes A row r0+i+1 into slot ic2, emits output row r0+i.
#define STEP(ia, ib, ic2, i) { \
    const int rr = r0 + (i); \
    float xv = pxv, yv = pyv; \
    rowcur = (rowcur < H - 1) ? rowcur + 1 : rowcur; \
    pxv = px[(size_t)rowcur * W]; \
    pyv = py[(size_t)rowcur * W]; \
    HQ(xv, yv, hx[ic2], hy[ic2], hxy[ic2], hxx[ic2]) \
    xc[ic2] = xv; \
    float hAn, hBn; \
    ABROW(hx[ia] + hx[ib] + hx[ic2], hy[ia] + hy[ib] + hy[ic2], \
          hxy[ia] + hxy[ib] + hxy[ic2], hxx[ia] + hxx[ib] + hxx[ic2], hAn, hBn) \
    if (rr + 1 >= H) { hAn = hA[ib]; hBn = hB[ib]; }   /* bottom: A(H):=A(H-1) */ \
    hA[ic2] = hAn; hB[ic2] = hBn; \
    float SA = hA[ia] + hA[ib] + hAn; \
    float SB = hB[ia] + hB[ib] + hBn; \
    float res = fmaf(SA * C9, xc[ia], SB * C9); \
    res = fminf(fmaxf(truncf(res), 0.0f), 255.0f); \
    if (do_store) *po = res; \
    po += W; }

    // CHUNK_H = 128 rows: 42 triples (i = 0..125) + i = 126, 127
    for (int i = 0; i < CHUNK_H - 2; i += 3) {
        STEP(0, 1, 2, i)
        STEP(1, 2, 0, i + 1)
        STEP(2, 0, 1, i + 2)
    }
    STEP(0, 1, 2, CHUNK_H - 2)
    STEP(1, 2, 0, CHUNK_H - 1)
#undef STEP
#undef ABROW
#undef HQ
}

extern "C" void kernel_launch(void* const* d_in, const int* in_sizes, int n_in,
                              void* d_out, int out_size) {
    const float* x = (const float*)d_in[0];
    const float* y = (const float*)d_in[1];
    float* out     = (float*)d_out;

    gf_kernel<<<NBLOCKS, 32 * WPB>>>(x, y, out);
}